// round 13
// baseline (speedup 1.0000x reference)
#include <cuda_runtime.h>
#include <math.h>

// Sampler: Gumbel-keys relaxed top-k. khot = sum_{t=1..k} softmax(att_g_t),
// att_g_{t+1} = att_g_t + log(max(1 - onehot_t, eps)).
// One CTA per row (B=128 rows, n=1024), all state in registers. Latency-chain
// bound. Per-sync structure (rotated loop):
//   LDS(prev reduction) -> scales rA,rB,rC (branchless-gated) ->
//   e-only rounds (snapshots kept) -> moments of new e ->
//   butterfly INTERLEAVED with deferred acc-FMAs + state copy (fills the
//   ~130cy shuffle-latency bubbles) -> STS -> BAR.
// Identities: fixed shift M0 (logits monotone non-increasing); unnormalized
// numerators oh=e/S; depth-3 fusion S2=S-P2/S, Q2=P2-(2P3-P4/S)/S,
// S3=S2-Q2/S2 gated on P2<0.99*S^2; rB/rC zeroed by remaining-steps
// predicates -> no separate tail (zero scale == exact no-op, zero acc term).

#define NTHREADS 128
#define NWARPS   (NTHREADS / 32)       // 4
#define NNODES   1024
#define EPT      (NNODES / NTHREADS)   // 8
#define EPS_F    1.1754943508222875e-38f  // np.finfo(float32).tiny
#define LOG2E    1.4426950408889634f

__device__ __forceinline__ float ex2_approx(float x) {
    float r; asm("ex2.approx.f32 %0, %1;" : "=f"(r) : "f"(x)); return r;
}
__device__ __forceinline__ float rcp_approx(float x) {
    float r; asm("rcp.approx.f32 %0, %1;" : "=f"(r) : "f"(x)); return r;
}
__device__ __forceinline__ float4 add4(float4 a, float4 b) {
    return make_float4(a.x + b.x, a.y + b.y, a.z + b.z, a.w + b.w);
}

__global__ __launch_bounds__(NTHREADS, 1)
void sampler_topk_kernel(const float* __restrict__ att,
                         const float* __restrict__ uni,
                         const int*  __restrict__ kptr,
                         float* __restrict__ out)
{
    // double-buffered per-warp moment vectors: single barrier per sync is
    // race-free (epoch e reads buf(e&1), writes buf((e+1)&1)).
    __shared__ __align__(16) float4 sm4[2][NWARPS];
    __shared__ __align__(16) float  sm_m[NWARPS];

    const int row  = blockIdx.x;
    const int tid  = threadIdx.x;
    const int lane = tid & 31;
    const int warp = tid >> 5;
    const int k    = *kptr;

    const float* __restrict__ arow = att + row * NNODES;
    const float* __restrict__ urow = uni + row * NNODES;
    float*       __restrict__ orow = out + row * NNODES;

    float e0[EPT], acc[EPT];

    // Gumbel init in log2 domain: b = (att - log(-log(u+eps))) * log2(e)
    {
        float b[EPT];
        float m = -3.402823466e38f;
        #pragma unroll
        for (int j = 0; j < EPT; ++j) {
            const int idx = tid + j * NTHREADS;      // coalesced
            float u = urow[idx];
            b[j] = (arow[idx] - logf(-logf(u + EPS_F))) * LOG2E;
            m = fmaxf(m, b[j]);
            acc[j] = 0.0f;
        }
        #pragma unroll
        for (int o = 16; o > 0; o >>= 1)
            m = fmaxf(m, __shfl_xor_sync(0xffffffffu, m, o));
        if (lane == 0) sm_m[warp] = m;
        __syncthreads();
        float4 mv = *(const float4*)&sm_m[0];
        float M = fmaxf(fmaxf(mv.x, mv.y), fmaxf(mv.z, mv.w));
        #pragma unroll
        for (int j = 0; j < EPT; ++j)
            e0[j] = ex2_approx(b[j] - M);            // unnormalized numerators
    }

    const bool tb0 = (lane & 1) != 0;
    const bool tb1 = (lane & 2) != 0;
    // smem write index for lanes 0..3 (moment permutation of the transpose):
    // lane&3: 0->S(0), 1->P3(2), 2->P2(1), 3->P4(3)
    const int widx = ((lane & 1) << 1) | ((lane >> 1) & 1);

    // ---- prologue reduction of the initial state (epoch writes buf 0) ----
    {
        float s = 0.f, p2 = 0.f, p3 = 0.f, p4 = 0.f;
        #pragma unroll
        for (int j = 0; j < EPT; ++j) {
            float x  = e0[j];
            float x2 = x * x;
            s  += x;
            p2 += x2;
            p3 = __fmaf_rn(x2, x,  p3);
            p4 = __fmaf_rn(x2, x2, p4);
        }
        float send0 = tb0 ? s  : p3;
        float send1 = tb0 ? p2 : p4;
        float r0 = __shfl_xor_sync(0xffffffffu, send0, 1);
        float r1 = __shfl_xor_sync(0xffffffffu, send1, 1);
        float a0 = (tb0 ? p3 : s)  + r0;
        float a1 = (tb0 ? p4 : p2) + r1;
        float send2 = tb1 ? a0 : a1;
        float r2 = __shfl_xor_sync(0xffffffffu, send2, 2);
        float c = (tb1 ? a1 : a0) + r2;
        c += __shfl_xor_sync(0xffffffffu, c, 4);
        c += __shfl_xor_sync(0xffffffffu, c, 8);
        c += __shfl_xor_sync(0xffffffffu, c, 16);
        if (lane < 4) ((float*)&sm4[0][warp])[widx] = c;
        __syncthreads();
    }

    int steps = 0;
    int it = 0;
    while (steps < k) {
        // ---- 1. consume previous reduction ----
        const float4* sv = &sm4[it & 1][0];
        float4 t = add4(add4(sv[0], sv[1]), add4(sv[2], sv[3]));
        const float S = t.x, P2 = t.y, P3 = t.z, P4 = t.w;

        const int rem = k - steps;
        float rA = rcp_approx(S);
        // round B scale (S2 = S - P2/S), zeroed if <2 steps remain
        float S2 = __fmaf_rn(-P2, rA, S);
        S2 = fmaxf(S2, S * 1e-6f);
        float rB = (rem >= 2) ? rcp_approx(S2) : 0.0f;
        // round C scale (S3 = S2 - Q2/S2), zeroed unless >=3 remain AND gate
        float u  = __fmaf_rn(-P4, rA, 2.0f * P3);    // 2*P3 - P4/S
        float Q2 = __fmaf_rn(-u, rA, P2);            // P2 - u/S
        Q2 = fminf(fmaxf(Q2, 0.0f), P2);
        float S3 = __fmaf_rn(-Q2, rB, S2);
        S3 = fmaxf(S3, S2 * 1e-6f);
        const bool gC = (rem >= 3) && (P2 < 0.99f * (S * S));
        float rC = gC ? rcp_approx(S3) : 0.0f;
        steps += 1 + (rB != 0.0f) + (rC != 0.0f);

        // ---- 2. e-only rounds, keeping snapshots for deferred acc ----
        float e1[EPT], e2[EPT], e3[EPT];
        #pragma unroll
        for (int j = 0; j < EPT; ++j) {
            float x = e0[j];
            float tA = x * x;
            e1[j] = __fmaf_rn(-tA, rA, x);           // x - x^2/S
            float tB = e1[j] * e1[j];
            e2[j] = __fmaf_rn(-tB, rB, e1[j]);
            float tC = e2[j] * e2[j];
            e3[j] = __fmaf_rn(-tC, rC, e2[j]);
        }
        // ---- 3. moments of the new state ----
        float s = 0.f, p2 = 0.f, p3 = 0.f, p4 = 0.f;
        #pragma unroll
        for (int j = 0; j < EPT; ++j) {
            float x  = e3[j];
            float x2 = x * x;
            s  += x;
            p2 += x2;
            p3 = __fmaf_rn(x2, x,  p3);
            p4 = __fmaf_rn(x2, x2, p4);
        }
        // ---- 4. butterfly, with deferred acc-FMAs + state copy filling the
        //         shuffle-latency bubbles (independent of the reduction) ----
        float send0 = tb0 ? s  : p3;
        float send1 = tb0 ? p2 : p4;
        float r0 = __shfl_xor_sync(0xffffffffu, send0, 1);
        float r1 = __shfl_xor_sync(0xffffffffu, send1, 1);
        #pragma unroll
        for (int j = 0; j < EPT; ++j)                // deferred: round-A acc
            acc[j] = __fmaf_rn(e0[j], rA, acc[j]);
        float a0 = (tb0 ? p3 : s)  + r0;
        float a1 = (tb0 ? p4 : p2) + r1;
        float send2 = tb1 ? a0 : a1;
        float r2 = __shfl_xor_sync(0xffffffffu, send2, 2);
        #pragma unroll
        for (int j = 0; j < EPT; ++j)                // deferred: round-B acc
            acc[j] = __fmaf_rn(e1[j], rB, acc[j]);
        float c = (tb1 ? a1 : a0) + r2;
        c += __shfl_xor_sync(0xffffffffu, c, 4);
        #pragma unroll
        for (int j = 0; j < EPT; ++j)                // deferred: round-C acc
            acc[j] = __fmaf_rn(e2[j], rC, acc[j]);
        c += __shfl_xor_sync(0xffffffffu, c, 8);
        #pragma unroll
        for (int j = 0; j < EPT; ++j)                // carry new state
            e0[j] = e3[j];
        c += __shfl_xor_sync(0xffffffffu, c, 16);
        if (lane < 4) ((float*)&sm4[(it + 1) & 1][warp])[widx] = c;
        __syncthreads();
        ++it;
    }

    #pragma unroll
    for (int j = 0; j < EPT; ++j)
        orow[tid + j * NTHREADS] = acc[j];
}

extern "C" void kernel_launch(void* const* d_in, const int* in_sizes, int n_in,
                              void* d_out, int out_size)
{
    const float* att = (const float*)d_in[0];
    const float* uni = (const float*)d_in[1];
    const int*   kp  = (const int*)d_in[2];
    float* out = (float*)d_out;

    const int B = in_sizes[0] / NNODES;   // 128
    sampler_topk_kernel<<<B, NTHREADS>>>(att, uni, kp, out);
}

// round 15
// speedup vs baseline: 1.0161x; 1.0161x over previous
#include <cuda_runtime.h>
#include <math.h>

// Sampler: Gumbel-keys relaxed top-k. khot = sum_{t=1..k} softmax(att_g_t),
// att_g_{t+1} = att_g_t + log(max(1 - onehot_t, eps)).
// One CTA per row (B=128 rows, n=1024), all state in registers. Latency-chain
// bound. R12 structure (moments -> butterfly -> STS -> BAR -> LDS -> scales ->
// rounds) with DATA-INDEPENDENT loop control:
//  - main loop trip count is FIXED at k/3 (counter-only branch; the old
//    while(steps<k) back-branch waited on the reduced S via rB/rC != 0).
//  - round B unconditional; round C gated (P2 < 0.99*S^2) via SELP only,
//    gate count accumulated in ng; step deficit covered by a depth-2 tail.
// Identities: fixed shift M0 (logits monotone non-increasing); unnormalized
// numerators oh=e/S; S2=S-P2/S; Q2=P2-(2P3-P4/S)/S; S3=S2-Q2/S2 (one-shot
// error: every sync re-reduces exact sums from the e registers).

#define NTHREADS 128
#define NWARPS   (NTHREADS / 32)       // 4
#define NNODES   1024
#define EPT      (NNODES / NTHREADS)   // 8
#define EPS_F    1.1754943508222875e-38f  // np.finfo(float32).tiny
#define LOG2E    1.4426950408889634f

__device__ __forceinline__ float ex2_approx(float x) {
    float r; asm("ex2.approx.f32 %0, %1;" : "=f"(r) : "f"(x)); return r;
}
__device__ __forceinline__ float rcp_approx(float x) {
    float r; asm("rcp.approx.f32 %0, %1;" : "=f"(r) : "f"(x)); return r;
}
__device__ __forceinline__ float4 add4(float4 a, float4 b) {
    return make_float4(a.x + b.x, a.y + b.y, a.z + b.z, a.w + b.w);
}

__global__ __launch_bounds__(NTHREADS, 1)
void sampler_topk_kernel(const float* __restrict__ att,
                         const float* __restrict__ uni,
                         const int*  __restrict__ kptr,
                         float* __restrict__ out)
{
    // double-buffered per-warp moment vectors: single barrier per sync is
    // race-free (write buf(t+2) after bar(t+1); reads of buf(t) between
    // bar(t) and bar(t+1)).
    __shared__ __align__(16) float4 sm4[2][NWARPS];
    __shared__ __align__(16) float  sm_m[NWARPS];

    const int row  = blockIdx.x;
    const int tid  = threadIdx.x;
    const int lane = tid & 31;
    const int warp = tid >> 5;
    const int k    = *kptr;

    const float* __restrict__ arow = att + row * NNODES;
    const float* __restrict__ urow = uni + row * NNODES;
    float*       __restrict__ orow = out + row * NNODES;

    float e[EPT], acc[EPT];

    // Gumbel init in log2 domain: b = (att - log(-log(u+eps))) * log2(e)
    {
        float b[EPT];
        float m = -3.402823466e38f;
        #pragma unroll
        for (int j = 0; j < EPT; ++j) {
            const int idx = tid + j * NTHREADS;      // coalesced
            float u = urow[idx];
            b[j] = (arow[idx] - logf(-logf(u + EPS_F))) * LOG2E;
            m = fmaxf(m, b[j]);
            acc[j] = 0.0f;
        }
        // one-time block max M0 (valid shift forever: logits only decrease)
        #pragma unroll
        for (int o = 16; o > 0; o >>= 1)
            m = fmaxf(m, __shfl_xor_sync(0xffffffffu, m, o));
        if (lane == 0) sm_m[warp] = m;
        __syncthreads();
        float4 mv = *(const float4*)&sm_m[0];
        float M = fmaxf(fmaxf(mv.x, mv.y), fmaxf(mv.z, mv.w));
        #pragma unroll
        for (int j = 0; j < EPT; ++j)
            e[j] = ex2_approx(b[j] - M);             // unnormalized numerators
    }

    const bool tb0 = (lane & 1) != 0;
    const bool tb1 = (lane & 2) != 0;
    // smem write index for lanes 0..3 (moment permutation of the transpose):
    // lane&3: 0->S(0), 1->P3(2), 2->P2(1), 3->P4(3)
    const int widx = ((lane & 1) << 1) | ((lane >> 1) & 1);

    const int nmain = k / 3;                         // 205 for k=615
    int ng = 0;                                      // gate-fire count

    for (int it = 0; it < nmain; ++it) {
        // ---- local moments: s, p2, p3, p4 (FMA-fused) ----
        float s = 0.f, p2 = 0.f, p3 = 0.f, p4 = 0.f;
        #pragma unroll
        for (int j = 0; j < EPT; ++j) {
            float x  = e[j];
            float x2 = x * x;
            s  += x;
            p2 = __fmaf_rn(x,  x,  p2);
            p3 = __fmaf_rn(x2, x,  p3);
            p4 = __fmaf_rn(x2, x2, p4);
        }
        // ---- transpose butterfly: 4 values reduced in 6 shfls ----
        float send0 = tb0 ? s  : p3;
        float send1 = tb0 ? p2 : p4;
        float r0 = __shfl_xor_sync(0xffffffffu, send0, 1);
        float r1 = __shfl_xor_sync(0xffffffffu, send1, 1);
        float a0 = (tb0 ? p3 : s)  + r0;
        float a1 = (tb0 ? p4 : p2) + r1;
        float send2 = tb1 ? a0 : a1;
        float r2 = __shfl_xor_sync(0xffffffffu, send2, 2);
        float c = (tb1 ? a1 : a0) + r2;
        c += __shfl_xor_sync(0xffffffffu, c, 4);
        c += __shfl_xor_sync(0xffffffffu, c, 8);
        c += __shfl_xor_sync(0xffffffffu, c, 16);
        const int buf = it & 1;
        if (lane < 4) ((float*)&sm4[buf][warp])[widx] = c;
        // ---- shadow work while the barrier drains: e^2 for round A ----
        float e2[EPT];
        #pragma unroll
        for (int j = 0; j < EPT; ++j) e2[j] = e[j] * e[j];
        __syncthreads();
        const float4* sv = &sm4[buf][0];
        float4 t = add4(add4(sv[0], sv[1]), add4(sv[2], sv[3]));
        const float S = t.x, P2 = t.y, P3 = t.z, P4 = t.w;

        // ---- round A: 2 instr/elem (e^2 precomputed) ----
        float rA = rcp_approx(S);
        #pragma unroll
        for (int j = 0; j < EPT; ++j) {
            acc[j] = __fmaf_rn(e[j], rA, acc[j]);
            e[j]   = __fmaf_rn(-e2[j], rA, e[j]);    // e - e^2/S
        }
        // ---- round B (unconditional): S2 = S - P2/S ----
        float S2 = __fmaf_rn(-P2, rA, S);
        S2 = fmaxf(S2, S * 1e-6f);
        float rB = rcp_approx(S2);
        #pragma unroll
        for (int j = 0; j < EPT; ++j) {
            float oh = e[j] * rB;
            acc[j] += oh;
            e[j] = __fmaf_rn(-oh, e[j], e[j]);
        }
        // ---- round C (SELP-gated, no branch): S3 = S2 - Q2/S2 ----
        float u  = __fmaf_rn(-P4, rA, 2.0f * P3);    // 2*P3 - P4/S
        float Q2 = __fmaf_rn(-u, rA, P2);            // P2 - u/S
        Q2 = fminf(fmaxf(Q2, 0.0f), P2);             // 0 <= Q2 <= P2
        float S3 = __fmaf_rn(-Q2, rB, S2);
        S3 = fmaxf(S3, S2 * 1e-6f);
        const bool g = P2 < 0.99f * (S * S);
        float rC = g ? rcp_approx(S3) : 0.0f;        // rC=0 -> exact no-op
        ng += (int)g;                                // off the branch path
        #pragma unroll
        for (int j = 0; j < EPT; ++j) {
            float oh = e[j] * rC;
            acc[j] += oh;
            e[j] = __fmaf_rn(-oh, e[j], e[j]);
        }
    }

    // ---- tail: remaining steps (rare; depth-2, branchless round B) ----
    int steps = 2 * nmain + ng;
    while (steps < k) {
        float s = 0.f, p2 = 0.f;
        #pragma unroll
        for (int j = 0; j < EPT; ++j) {
            s  += e[j];
            p2 = __fmaf_rn(e[j], e[j], p2);
        }
        #pragma unroll
        for (int o = 16; o > 0; o >>= 1) {
            s  += __shfl_xor_sync(0xffffffffu, s,  o);
            p2 += __shfl_xor_sync(0xffffffffu, p2, o);
        }
        __syncthreads();                 // protect sm_m across tail iters
        if (lane == 0) sm_m[warp] = s;
        __syncthreads();
        float4 sv = *(const float4*)&sm_m[0];
        float S = (sv.x + sv.y) + (sv.z + sv.w);
        __syncthreads();
        if (lane == 0) sm_m[warp] = p2;
        __syncthreads();
        float4 pv = *(const float4*)&sm_m[0];
        float P2 = (pv.x + pv.y) + (pv.z + pv.w);

        float rA = rcp_approx(S);
        #pragma unroll
        for (int j = 0; j < EPT; ++j) {
            float oh = e[j] * rA;
            acc[j] += oh;
            e[j] = __fmaf_rn(-oh, e[j], e[j]);
        }
        float S2 = __fmaf_rn(-P2, rA, S);
        S2 = fmaxf(S2, S * 1e-6f);
        float rB = (steps + 2 <= k) ? rcp_approx(S2) : 0.0f;
        #pragma unroll
        for (int j = 0; j < EPT; ++j) {
            float oh = e[j] * rB;
            acc[j] += oh;
            e[j] = __fmaf_rn(-oh, e[j], e[j]);
        }
        steps += 1 + (rB != 0.0f);
    }

    #pragma unroll
    for (int j = 0; j < EPT; ++j)
        orow[tid + j * NTHREADS] = acc[j];
}

extern "C" void kernel_launch(void* const* d_in, const int* in_sizes, int n_in,
                              void* d_out, int out_size)
{
    const float* att = (const float*)d_in[0];
    const float* uni = (const float*)d_in[1];
    const int*   kp  = (const int*)d_in[2];
    float* out = (float*)d_out;

    const int B = in_sizes[0] / NNODES;   // 128
    sampler_topk_kernel<<<B, NTHREADS>>>(att, uni, kp, out);
}

// round 17
// speedup vs baseline: 1.0887x; 1.0714x over previous
#include <cuda_runtime.h>
#include <math.h>

// Sampler: Gumbel-keys relaxed top-k. khot = sum_{t=1..k} softmax(att_g_t),
// att_g_{t+1} = att_g_t + log(max(1 - onehot_t, eps)).
// One CTA per row (B=128 rows, n=1024), all state in registers. Jointly
// issue- and latency-bound -> maximize steps per barrier round-trip at
// CONSTANT moment count (S,P2,P3,P4):
//   round A: rA = 1/S                       (exact)
//   round B: S1 = S - P2/S                  (exact)
//   round C: Q1 = P2 - (2P3 - P4/S)/S;  S2 = S1 - Q1/S1   (exact, gate rho0)
//   round D: R3^ = P3 - 3P4/S  (2nd-order); Q2^ = Q1 - (2R3^ - P4/S1)/S1;
//            S3^ = S2 - Q2^/S2              (gated HARD on rho1 = Q1/S1^2
//                                            < 0.02 -> error <= ~4e-4, one-
//                                            shot: next sync re-reduces exact
//                                            sums from the e registers)
// Plus: fixed softmax shift M0 (logits monotone non-increasing); unnormalized
// numerators oh=e/S; 128 thr / 4 warps (1/SMSP); 6-shfl transpose butterfly;
// single double-buffered barrier per sync.

#define NTHREADS 128
#define NWARPS   (NTHREADS / 32)       // 4
#define NNODES   1024
#define EPT      (NNODES / NTHREADS)   // 8
#define EPS_F    1.1754943508222875e-38f  // np.finfo(float32).tiny
#define LOG2E    1.4426950408889634f

__device__ __forceinline__ float ex2_approx(float x) {
    float r; asm("ex2.approx.f32 %0, %1;" : "=f"(r) : "f"(x)); return r;
}
__device__ __forceinline__ float rcp_approx(float x) {
    float r; asm("rcp.approx.f32 %0, %1;" : "=f"(r) : "f"(x)); return r;
}
__device__ __forceinline__ float4 add4(float4 a, float4 b) {
    return make_float4(a.x + b.x, a.y + b.y, a.z + b.z, a.w + b.w);
}

__global__ __launch_bounds__(NTHREADS, 1)
void sampler_topk_kernel(const float* __restrict__ att,
                         const float* __restrict__ uni,
                         const int*  __restrict__ kptr,
                         float* __restrict__ out)
{
    // double-buffered per-warp moment vectors: single barrier per sync is
    // race-free (write buf(t+2) after bar(t+1); reads of buf(t) between
    // bar(t) and bar(t+1)).
    __shared__ __align__(16) float4 sm4[2][NWARPS];
    __shared__ __align__(16) float  sm_m[NWARPS];

    const int row  = blockIdx.x;
    const int tid  = threadIdx.x;
    const int lane = tid & 31;
    const int warp = tid >> 5;
    const int k    = *kptr;

    const float* __restrict__ arow = att + row * NNODES;
    const float* __restrict__ urow = uni + row * NNODES;
    float*       __restrict__ orow = out + row * NNODES;

    float e[EPT], acc[EPT];

    // Gumbel init in log2 domain: b = (att - log(-log(u+eps))) * log2(e)
    {
        float b[EPT];
        float m = -3.402823466e38f;
        #pragma unroll
        for (int j = 0; j < EPT; ++j) {
            const int idx = tid + j * NTHREADS;      // coalesced
            float u = urow[idx];
            b[j] = (arow[idx] - logf(-logf(u + EPS_F))) * LOG2E;
            m = fmaxf(m, b[j]);
            acc[j] = 0.0f;
        }
        // one-time block max M0 (valid shift forever: logits only decrease)
        #pragma unroll
        for (int o = 16; o > 0; o >>= 1)
            m = fmaxf(m, __shfl_xor_sync(0xffffffffu, m, o));
        if (lane == 0) sm_m[warp] = m;
        __syncthreads();
        float4 mv = *(const float4*)&sm_m[0];
        float M = fmaxf(fmaxf(mv.x, mv.y), fmaxf(mv.z, mv.w));
        #pragma unroll
        for (int j = 0; j < EPT; ++j)
            e[j] = ex2_approx(b[j] - M);             // unnormalized numerators
    }

    const bool tb0 = (lane & 1) != 0;
    const bool tb1 = (lane & 2) != 0;
    // smem write index for lanes 0..3 (moment permutation of the transpose):
    // lane&3: 0->S(0), 1->P3(2), 2->P2(1), 3->P4(3)
    const int widx = ((lane & 1) << 1) | ((lane >> 1) & 1);

    int steps = 0;
    int it = 0;
    while (steps <= k - 4) {
        // ---- local moments: s, p2, p3, p4 (FMA-fused) ----
        float s = 0.f, p2 = 0.f, p3 = 0.f, p4 = 0.f;
        #pragma unroll
        for (int j = 0; j < EPT; ++j) {
            float x  = e[j];
            float x2 = x * x;
            s  += x;
            p2 = __fmaf_rn(x,  x,  p2);
            p3 = __fmaf_rn(x2, x,  p3);
            p4 = __fmaf_rn(x2, x2, p4);
        }
        // ---- transpose butterfly: 4 values reduced in 6 shfls ----
        float send0 = tb0 ? s  : p3;
        float send1 = tb0 ? p2 : p4;
        float r0 = __shfl_xor_sync(0xffffffffu, send0, 1);
        float r1 = __shfl_xor_sync(0xffffffffu, send1, 1);
        float a0 = (tb0 ? p3 : s)  + r0;
        float a1 = (tb0 ? p4 : p2) + r1;
        float send2 = tb1 ? a0 : a1;
        float r2 = __shfl_xor_sync(0xffffffffu, send2, 2);
        float c = (tb1 ? a1 : a0) + r2;
        c += __shfl_xor_sync(0xffffffffu, c, 4);
        c += __shfl_xor_sync(0xffffffffu, c, 8);
        c += __shfl_xor_sync(0xffffffffu, c, 16);
        const int buf = it & 1;
        if (lane < 4) ((float*)&sm4[buf][warp])[widx] = c;
        // ---- shadow work while the barrier drains: e^2 for round A ----
        float e2[EPT];
        #pragma unroll
        for (int j = 0; j < EPT; ++j) e2[j] = e[j] * e[j];
        __syncthreads();
        const float4* sv = &sm4[buf][0];
        float4 t = add4(add4(sv[0], sv[1]), add4(sv[2], sv[3]));
        const float S = t.x, P2 = t.y, P3 = t.z, P4 = t.w;

        // ---- scalar ladder (uniform; off the element path) ----
        float rA = rcp_approx(S);
        float S1 = __fmaf_rn(-P2, rA, S);            // exact
        S1 = fmaxf(S1, S * 1e-6f);
        float rB = rcp_approx(S1);
        float u  = __fmaf_rn(-P4, rA, 2.0f * P3);    // 2P3 - P4/S
        float Q1 = __fmaf_rn(-u, rA, P2);            // exact sum e1^2
        Q1 = fminf(fmaxf(Q1, 0.0f), P2);
        float S2 = __fmaf_rn(-Q1, rB, S1);           // exact
        S2 = fmaxf(S2, S1 * 1e-6f);
        const bool gC = P2 < 0.99f * (S * S);
        float rC = gC ? rcp_approx(S2) : 0.0f;       // rC=0 -> exact no-op
        // round D (2nd-order, hard-gated on rho1 = Q1/S1^2 < 0.02)
        float R3h = fmaxf(__fmaf_rn(-3.0f * P4, rA, P3), 0.0f);
        float uD  = __fmaf_rn(-P4, rB, 2.0f * R3h);  // 2R3^ - P4/S1
        float Q2h = __fmaf_rn(-uD, rB, Q1);
        Q2h = fminf(fmaxf(Q2h, 0.0f), Q1);
        float S3h = __fmaf_rn(-Q2h, rC, S2);         // rC = 1/S2 when gC
        S3h = fmaxf(S3h, S2 * 1e-6f);
        const bool gD = gC && (Q1 < 0.02f * (S1 * S1));
        float rD = gD ? rcp_approx(S3h) : 0.0f;
        steps += 2 + (int)gC + (int)gD;

        // ---- element rounds ----
        #pragma unroll
        for (int j = 0; j < EPT; ++j) {              // A (e^2 precomputed)
            acc[j] = __fmaf_rn(e[j], rA, acc[j]);
            e[j]   = __fmaf_rn(-e2[j], rA, e[j]);
        }
        #pragma unroll
        for (int j = 0; j < EPT; ++j) {              // B
            float oh = e[j] * rB;
            acc[j] += oh;
            e[j] = __fmaf_rn(-oh, e[j], e[j]);
        }
        #pragma unroll
        for (int j = 0; j < EPT; ++j) {              // C
            float oh = e[j] * rC;
            acc[j] += oh;
            e[j] = __fmaf_rn(-oh, e[j], e[j]);
        }
        #pragma unroll
        for (int j = 0; j < EPT; ++j) {              // D
            float oh = e[j] * rD;
            acc[j] += oh;
            e[j] = __fmaf_rn(-oh, e[j], e[j]);
        }
        ++it;
    }

    // ---- tail: <=3 single steps (sum-only reduction) ----
    while (steps < k) {
        float s = 0.f;
        #pragma unroll
        for (int j = 0; j < EPT; ++j) s += e[j];
        #pragma unroll
        for (int o = 16; o > 0; o >>= 1)
            s += __shfl_xor_sync(0xffffffffu, s, o);
        __syncthreads();                 // protect sm_m across tail iters
        if (lane == 0) sm_m[warp] = s;
        __syncthreads();
        float4 sv = *(const float4*)&sm_m[0];
        float S = (sv.x + sv.y) + (sv.z + sv.w);
        float r = rcp_approx(S);
        #pragma unroll
        for (int j = 0; j < EPT; ++j) {
            float oh = e[j] * r;
            acc[j] += oh;
            e[j] = __fmaf_rn(-oh, e[j], e[j]);
        }
        steps += 1;
    }

    #pragma unroll
    for (int j = 0; j < EPT; ++j)
        orow[tid + j * NTHREADS] = acc[j];
}

extern "C" void kernel_launch(void* const* d_in, const int* in_sizes, int n_in,
                              void* d_out, int out_size)
{
    const float* att = (const float*)d_in[0];
    const float* uni = (const float*)d_in[1];
    const int*   kp  = (const int*)d_in[2];
    float* out = (float*)d_out;

    const int B = in_sizes[0] / NNODES;   // 128
    sampler_topk_kernel<<<B, NTHREADS>>>(att, uni, kp, out);
}